// round 1
// baseline (speedup 1.0000x reference)
#include <cuda_runtime.h>
#include <cuda_bf16.h>
#include <math.h>

// Problem constants
#define N_MAX      50000
#define MEM_DIM    100
#define RAW        64          // msg rows per node
#define TIN        20          // msg row width
#define D_MSG      292         // 3*64 + 100
#define KPAD       400         // padded K (292 x + 100 mem + 8 zero)
#define JPAD       512         // padded output cols (4 groups of 128, 100 used each)

// Scratch (static device globals — no allocation allowed)
__device__ float g_A[(size_t)N_MAX * KPAD];   // 80 MB   [N][400] = [x(292) | mem(100) | 0(8)]
__device__ float g_B[(size_t)JPAD * KPAD];    // 0.8 MB  [512][400]
__device__ float g_C[(size_t)N_MAX * JPAD];   // 102 MB  [N][512]

// ---------------------------------------------------------------------------
// Kernel 0: build padded weight matrix.
// group 0 (j=  0..127): rsum  row c: [w_ih[c]       | w_hh[c]       ]
// group 1 (j=128..255): zsum  row c: [w_ih[100+c]   | w_hh[100+c]   ]
// group 2 (j=256..383): gi_n  row c: [w_ih[200+c]   | 0             ]
// group 3 (j=384..511): gh_n  row c: [0             | w_hh[200+c]   ]
// ---------------------------------------------------------------------------
__global__ void buildB(const float* __restrict__ wih, const float* __restrict__ whh) {
    int idx = blockIdx.x * blockDim.x + threadIdx.x;
    if (idx >= JPAD * KPAD) return;
    int j = idx / KPAD, k = idx % KPAD;
    int g = j >> 7, c = j & 127;
    float v = 0.0f;
    if (c < 100) {
        if (g == 0) {
            if (k < 292) v = wih[c * 292 + k];
            else if (k < 392) v = whh[c * 100 + (k - 292)];
        } else if (g == 1) {
            if (k < 292) v = wih[(100 + c) * 292 + k];
            else if (k < 392) v = whh[(100 + c) * 100 + (k - 292)];
        } else if (g == 2) {
            if (k < 292) v = wih[(200 + c) * 292 + k];
        } else {
            if (k >= 292 && k < 392) v = whh[(200 + c) * 100 + (k - 292)];
        }
    }
    g_B[idx] = v;
}

// ---------------------------------------------------------------------------
// Kernel 1: per-node message MLP + layernorms -> A row.
// One block (128 threads) per node.
// ---------------------------------------------------------------------------
__global__ __launch_bounds__(128) void phase1(
    const int* __restrict__ n_id,
    const float* __restrict__ memory,
    const float* __restrict__ msgs,
    const float* __restrict__ w1, const float* __restrict__ b1,
    const float* __restrict__ w2, const float* __restrict__ b2,
    const float* __restrict__ lg, const float* __restrict__ lb,
    const float* __restrict__ lng, const float* __restrict__ lnb,
    int N)
{
    __shared__ float sm[RAW * TIN];     // 1280 msg values
    __shared__ float sv[D_MSG];         // [mem(100) | comp(192)]
    __shared__ float red[8];
    __shared__ float s_mu, s_rs;

    int i = blockIdx.x;
    if (i >= N) return;
    int tid = threadIdx.x;
    int row = n_id[i];

    const float* src = msgs + (size_t)row * (RAW * TIN);
    for (int t = tid; t < RAW * TIN; t += 128) sm[t] = src[t];
    const float* memrow = memory + (size_t)row * MEM_DIM;
    if (tid < MEM_DIM) sv[tid] = memrow[tid];
    __syncthreads();

    if (tid < RAW) {
        const float* mr = sm + tid * TIN;
        float h[10];
#pragma unroll
        for (int j = 0; j < 10; j++) {
            float s = __ldg(b1 + j);
#pragma unroll
            for (int t = 0; t < TIN; t++) s += mr[t] * __ldg(w1 + j * TIN + t);
            h[j] = 0.5f * s * (1.0f + erff(s * 0.7071067811865476f));  // exact GELU
        }
        float y[3];
#pragma unroll
        for (int o = 0; o < 3; o++) {
            float s = __ldg(b2 + o);
#pragma unroll
            for (int j = 0; j < 10; j++) s += h[j] * __ldg(w2 + o * 10 + j);
            y[o] = s;
        }
        float mu = (y[0] + y[1] + y[2]) * (1.0f / 3.0f);
        float d0 = y[0] - mu, d1 = y[1] - mu, d2 = y[2] - mu;
        float var = (d0 * d0 + d1 * d1 + d2 * d2) * (1.0f / 3.0f);
        float rs = rsqrtf(var + 1e-5f);
        sv[MEM_DIM + 3 * tid + 0] = d0 * rs * __ldg(lg + 0) + __ldg(lb + 0);
        sv[MEM_DIM + 3 * tid + 1] = d1 * rs * __ldg(lg + 1) + __ldg(lb + 1);
        sv[MEM_DIM + 3 * tid + 2] = d2 * rs * __ldg(lg + 2) + __ldg(lb + 2);
    }
    __syncthreads();

    // Layernorm over 292
    float s1 = 0.0f, s2 = 0.0f;
    for (int k = tid; k < D_MSG; k += 128) { float v = sv[k]; s1 += v; s2 += v * v; }
#pragma unroll
    for (int o = 16; o > 0; o >>= 1) {
        s1 += __shfl_down_sync(0xFFFFFFFFu, s1, o);
        s2 += __shfl_down_sync(0xFFFFFFFFu, s2, o);
    }
    if ((tid & 31) == 0) { red[tid >> 5] = s1; red[4 + (tid >> 5)] = s2; }
    __syncthreads();
    if (tid == 0) {
        float t1 = red[0] + red[1] + red[2] + red[3];
        float t2 = red[4] + red[5] + red[6] + red[7];
        float mu = t1 * (1.0f / 292.0f);
        float var = t2 * (1.0f / 292.0f) - mu * mu;
        s_mu = mu;
        s_rs = rsqrtf(var + 1e-5f);
    }
    __syncthreads();

    float mu = s_mu, rs = s_rs;
    float* Ai = g_A + (size_t)i * KPAD;
    for (int k = tid; k < D_MSG; k += 128)
        Ai[k] = (sv[k] - mu) * rs * __ldg(lng + k) + __ldg(lnb + k);
    if (tid < MEM_DIM) Ai[D_MSG + tid] = sv[tid];   // raw mem at k 292..391
    if (tid < 8) Ai[392 + tid] = 0.0f;              // zero pad k 392..399
}

// ---------------------------------------------------------------------------
// Kernel 2: SGEMM  C[N][512] = A[N][400] * B[512][400]^T
// 128x128 block tile, BK=8, 256 threads, 8x8 register tile.
// ---------------------------------------------------------------------------
#define BM 128
#define BN 128
#define BK 8
__global__ __launch_bounds__(256) void gemm(int M) {
    __shared__ float As[BK][BM];
    __shared__ float Bs[BK][BN];

    int bm = blockIdx.x, bn = blockIdx.y;
    int tid = threadIdx.x;
    int tx = tid & 15, ty = tid >> 4;

    float acc[8][8];
#pragma unroll
    for (int u = 0; u < 8; u++)
#pragma unroll
        for (int v = 0; v < 8; v++) acc[u][v] = 0.0f;

    int arow0 = bm * BM, brow0 = bn * BN;
    int lr = tid >> 1, lc = (tid & 1) * 4;   // each thread loads one float4

    for (int kt = 0; kt < KPAD; kt += BK) {
        int ar = arow0 + lr;
        float4 av = make_float4(0.f, 0.f, 0.f, 0.f);
        if (ar < M) av = *(const float4*)(g_A + (size_t)ar * KPAD + kt + lc);
        As[lc + 0][lr] = av.x; As[lc + 1][lr] = av.y;
        As[lc + 2][lr] = av.z; As[lc + 3][lr] = av.w;

        float4 bv = *(const float4*)(g_B + (size_t)(brow0 + lr) * KPAD + kt + lc);
        Bs[lc + 0][lr] = bv.x; Bs[lc + 1][lr] = bv.y;
        Bs[lc + 2][lr] = bv.z; Bs[lc + 3][lr] = bv.w;
        __syncthreads();

#pragma unroll
        for (int k = 0; k < BK; k++) {
            float ra[8], rb[8];
#pragma unroll
            for (int u = 0; u < 8; u++) ra[u] = As[k][ty * 8 + u];
#pragma unroll
            for (int v = 0; v < 8; v++) rb[v] = Bs[k][tx * 8 + v];
#pragma unroll
            for (int u = 0; u < 8; u++)
#pragma unroll
                for (int v = 0; v < 8; v++) acc[u][v] = fmaf(ra[u], rb[v], acc[u][v]);
        }
        __syncthreads();
    }

#pragma unroll
    for (int u = 0; u < 8; u++) {
        int r = arow0 + ty * 8 + u;
        if (r < M) {
#pragma unroll
            for (int v = 0; v < 8; v++)
                g_C[(size_t)r * JPAD + brow0 + tx * 8 + v] = acc[u][v];
        }
    }
}

// ---------------------------------------------------------------------------
// Kernel 3: GRU gate epilogue
// ---------------------------------------------------------------------------
__global__ void epilogue(float* __restrict__ out, int N) {
    int idx = blockIdx.x * blockDim.x + threadIdx.x;
    if (idx >= N * MEM_DIM) return;
    int i = idx / MEM_DIM, c = idx % MEM_DIM;
    const float* Ci = g_C + (size_t)i * JPAD;
    float rsum = Ci[c];
    float zsum = Ci[128 + c];
    float gin  = Ci[256 + c];
    float ghn  = Ci[384 + c];
    float mem  = g_A[(size_t)i * KPAD + D_MSG + c];
    float r = 1.0f / (1.0f + expf(-rsum));
    float z = 1.0f / (1.0f + expf(-zsum));
    float n = tanhf(fmaf(r, ghn, gin));
    out[idx] = (1.0f - z) * n + z * mem;
}

// ---------------------------------------------------------------------------
extern "C" void kernel_launch(void* const* d_in, const int* in_sizes, int n_in,
                              void* d_out, int out_size) {
    const int*   n_id   = (const int*)d_in[0];
    const float* memory = (const float*)d_in[1];
    const float* msgs   = (const float*)d_in[2];
    const float* w1     = (const float*)d_in[3];
    const float* b1     = (const float*)d_in[4];
    const float* w2     = (const float*)d_in[5];
    const float* b2     = (const float*)d_in[6];
    const float* lg     = (const float*)d_in[7];
    const float* lb     = (const float*)d_in[8];
    const float* lng    = (const float*)d_in[9];
    const float* lnb    = (const float*)d_in[10];
    const float* wih    = (const float*)d_in[11];
    const float* whh    = (const float*)d_in[12];
    float* out = (float*)d_out;

    int N = in_sizes[0];
    if (N > N_MAX) N = N_MAX;

    // 0: pack weights
    buildB<<<(JPAD * KPAD + 255) / 256, 256>>>(wih, whh);

    // 1: message MLP + layernorms -> A
    phase1<<<N, 128>>>(n_id, memory, msgs, w1, b1, w2, b2, lg, lb, lng, lnb, N);

    // 2: GEMM
    dim3 grid((N + BM - 1) / BM, JPAD / BN);
    gemm<<<grid, 256>>>(N);

    // 3: GRU combine
    epilogue<<<(N * MEM_DIM + 255) / 256, 256>>>(out, N);
}

// round 3
// speedup vs baseline: 1.4367x; 1.4367x over previous
#include <cuda_runtime.h>
#include <cuda_bf16.h>
#include <math.h>
#include <stdint.h>

// ---------------- problem constants ----------------
#define N_MAXN    50000
#define NPAD      50048          // 782 * 64
#define MEM_DIM   100
#define RAW       64
#define TIN       20
#define D_MSG     292
#define KT1       448            // K per split term (400 real + pad)
#define AK        896            // A storage row: [Ahi(448) | Alo(448)]
#define KTOT      1344           // GEMM K: [term0 | term1 | term2]
#define JPAD      512            // 4 groups at 0/128/256/384, 100 used each

// ---------------- scratch ----------------
__device__ __nv_bfloat16 g_A[(size_t)NPAD * AK];    // ~90 MB
__device__ __nv_bfloat16 g_B[(size_t)JPAD * KTOT];  // ~1.4 MB
__device__ float         g_C[(size_t)NPAD * JPAD];  // ~102 MB
__device__ float         g_mem[(size_t)NPAD * MEM_DIM];

__device__ __forceinline__ uint32_t smem_u32(const void* p) {
    uint32_t a;
    asm("{ .reg .u64 t; cvta.to.shared.u64 t, %1; cvt.u32.u64 %0, t; }" : "=r"(a) : "l"(p));
    return a;
}
__device__ __forceinline__ void cp_async16(uint32_t dst, const void* src) {
    asm volatile("cp.async.cg.shared.global [%0], [%1], 16;" :: "r"(dst), "l"(src));
}
__device__ __forceinline__ void cp_commit() {
    asm volatile("cp.async.commit_group;" ::: "memory");
}
__device__ __forceinline__ void cp_wait_all() {
    asm volatile("cp.async.wait_group 0;" ::: "memory");
}
__device__ __forceinline__ void ldmx4(uint32_t* r, uint32_t addr) {
    asm volatile("ldmatrix.sync.aligned.m8n8.x4.shared.b16 {%0,%1,%2,%3}, [%4];"
        : "=r"(r[0]), "=r"(r[1]), "=r"(r[2]), "=r"(r[3]) : "r"(addr));
}
__device__ __forceinline__ void mma16816(float* d, const uint32_t* a, const uint32_t* b) {
    asm volatile(
        "mma.sync.aligned.m16n8k16.row.col.f32.bf16.bf16.f32 "
        "{%0,%1,%2,%3}, {%4,%5,%6,%7}, {%8,%9}, {%0,%1,%2,%3};"
        : "+f"(d[0]), "+f"(d[1]), "+f"(d[2]), "+f"(d[3])
        : "r"(a[0]), "r"(a[1]), "r"(a[2]), "r"(a[3]), "r"(b[0]), "r"(b[1]));
}
__device__ __forceinline__ void bsplit(float x, __nv_bfloat16& h, __nv_bfloat16& l) {
    h = __float2bfloat16(x);
    l = __float2bfloat16(x - __bfloat162float(h));
}

// ---------------------------------------------------------------------------
// Kernel 0: pack GRU weights -> g_B [512][1344] bf16, terms [Bhi|Blo|Bhi].
// group g = j/128 (r,z,gi_n,gh_n), c = j%128 (<100 used).
// kk = k%448: [0,292)=w_ih, [292,392)=w_hh, else 0.
// ---------------------------------------------------------------------------
__global__ void buildB(const float* __restrict__ wih, const float* __restrict__ whh) {
    int idx = blockIdx.x * blockDim.x + threadIdx.x;
    if (idx >= JPAD * KTOT) return;
    int j = idx / KTOT, k = idx % KTOT;
    int g = j >> 7, c = j & 127;
    int t = k / KT1, kk = k % KT1;
    float v = 0.0f;
    if (c < 100) {
        if (kk < D_MSG) {
            if (g == 0) v = wih[c * D_MSG + kk];
            else if (g == 1) v = wih[(100 + c) * D_MSG + kk];
            else if (g == 2) v = wih[(200 + c) * D_MSG + kk];
        } else if (kk < D_MSG + MEM_DIM) {
            int m = kk - D_MSG;
            if (g == 0) v = whh[c * MEM_DIM + m];
            else if (g == 1) v = whh[(100 + c) * MEM_DIM + m];
            else if (g == 3) v = whh[(200 + c) * MEM_DIM + m];
        }
    }
    __nv_bfloat16 h, l;
    bsplit(v, h, l);
    g_B[idx] = (t == 1) ? l : h;
}

// ---------------------------------------------------------------------------
// Kernel 1: per-node msg MLP + layernorms -> g_A row [hi(448)|lo(448)] + g_mem.
// ---------------------------------------------------------------------------
__global__ __launch_bounds__(128) void phase1(
    const int* __restrict__ n_id,
    const float* __restrict__ memory,
    const float* __restrict__ msgs,
    const float* __restrict__ w1, const float* __restrict__ b1,
    const float* __restrict__ w2, const float* __restrict__ b2,
    const float* __restrict__ lg, const float* __restrict__ lb,
    const float* __restrict__ lng, const float* __restrict__ lnb,
    int N)
{
    __shared__ float sm[RAW * TIN];
    __shared__ float sv[D_MSG];          // [mem(100) | comp(192)]
    __shared__ float red[8];
    __shared__ float s_mu, s_rs;

    int i = blockIdx.x;
    int tid = threadIdx.x;
    size_t base = (size_t)i * AK;

    if (i >= N) {  // zero pad rows
        __nv_bfloat16 z = __float2bfloat16(0.0f);
        for (int k = tid; k < AK; k += 128) g_A[base + k] = z;
        return;
    }
    int row = n_id[i];

    const float* src = msgs + (size_t)row * (RAW * TIN);
    for (int t = tid; t < RAW * TIN; t += 128) sm[t] = src[t];
    const float* memrow = memory + (size_t)row * MEM_DIM;
    if (tid < MEM_DIM) sv[tid] = memrow[tid];
    __syncthreads();

    if (tid < RAW) {
        const float* mr = sm + tid * TIN;
        float h[10];
#pragma unroll
        for (int j = 0; j < 10; j++) {
            float s = __ldg(b1 + j);
#pragma unroll
            for (int t = 0; t < TIN; t++) s += mr[t] * __ldg(w1 + j * TIN + t);
            h[j] = 0.5f * s * (1.0f + erff(s * 0.7071067811865476f));
        }
        float y[3];
#pragma unroll
        for (int o = 0; o < 3; o++) {
            float s = __ldg(b2 + o);
#pragma unroll
            for (int j = 0; j < 10; j++) s += h[j] * __ldg(w2 + o * 10 + j);
            y[o] = s;
        }
        float mu = (y[0] + y[1] + y[2]) * (1.0f / 3.0f);
        float d0 = y[0] - mu, d1 = y[1] - mu, d2 = y[2] - mu;
        float var = (d0 * d0 + d1 * d1 + d2 * d2) * (1.0f / 3.0f);
        float rs = rsqrtf(var + 1e-5f);
        sv[MEM_DIM + 3 * tid + 0] = d0 * rs * __ldg(lg + 0) + __ldg(lb + 0);
        sv[MEM_DIM + 3 * tid + 1] = d1 * rs * __ldg(lg + 1) + __ldg(lb + 1);
        sv[MEM_DIM + 3 * tid + 2] = d2 * rs * __ldg(lg + 2) + __ldg(lb + 2);
    }
    __syncthreads();

    float s1 = 0.0f, s2 = 0.0f;
    for (int k = tid; k < D_MSG; k += 128) { float v = sv[k]; s1 += v; s2 += v * v; }
#pragma unroll
    for (int o = 16; o > 0; o >>= 1) {
        s1 += __shfl_down_sync(0xFFFFFFFFu, s1, o);
        s2 += __shfl_down_sync(0xFFFFFFFFu, s2, o);
    }
    if ((tid & 31) == 0) { red[tid >> 5] = s1; red[4 + (tid >> 5)] = s2; }
    __syncthreads();
    if (tid == 0) {
        float t1 = red[0] + red[1] + red[2] + red[3];
        float t2 = red[4] + red[5] + red[6] + red[7];
        float mu = t1 * (1.0f / 292.0f);
        float var = t2 * (1.0f / 292.0f) - mu * mu;
        s_mu = mu;
        s_rs = rsqrtf(var + 1e-5f);
    }
    __syncthreads();

    float mu = s_mu, rs = s_rs;
    for (int k = tid; k < D_MSG; k += 128) {
        float v = (sv[k] - mu) * rs * __ldg(lng + k) + __ldg(lnb + k);
        __nv_bfloat16 h, l; bsplit(v, h, l);
        g_A[base + k] = h; g_A[base + KT1 + k] = l;
    }
    if (tid < MEM_DIM) {
        float v = sv[tid];
        __nv_bfloat16 h, l; bsplit(v, h, l);
        g_A[base + D_MSG + tid] = h; g_A[base + KT1 + D_MSG + tid] = l;
        g_mem[(size_t)i * MEM_DIM + tid] = v;
    }
    {
        __nv_bfloat16 z = __float2bfloat16(0.0f);
        for (int k = 392 + tid; k < KT1; k += 128) { g_A[base + k] = z; g_A[base + KT1 + k] = z; }
    }
}

// ---------------------------------------------------------------------------
// Kernel 2: bf16 HMMA GEMM  C[NPAD][512] = A * B^T   (K = 1344, 3-term split)
// BM=64 BN=128 BK=32, 256 threads, 8 warps (2x4, warp tile 32x32),
// cp.async double buffer, padded smem stride 40 halves.
// ---------------------------------------------------------------------------
#define BM 64
#define BN 128
#define BK 32
#define LDS 40
#define NKT (KTOT / BK)   // 42

__global__ __launch_bounds__(256, 2) void gemm3() {
    __shared__ __align__(16) uint16_t As[2][BM * LDS];
    __shared__ __align__(16) uint16_t Bs[2][BN * LDS];

    int tid = threadIdx.x;
    int lane = tid & 31, wid = tid >> 5;
    int wm = wid & 1, wn = wid >> 1;            // 2 x 4 warp grid
    int row0 = blockIdx.x * BM;
    int col0 = blockIdx.y * BN;

    const uint16_t* gA = (const uint16_t*)g_A;
    const uint16_t* gB = (const uint16_t*)g_B;

    float acc[2][4][4];
#pragma unroll
    for (int mf = 0; mf < 2; mf++)
#pragma unroll
        for (int nf = 0; nf < 4; nf++)
#pragma unroll
            for (int q = 0; q < 4; q++) acc[mf][nf][q] = 0.0f;

    // loader: A chunk per thread (r=tid/4, c=tid%4), B two chunks.
    int lr = tid >> 2, lc = tid & 3;

    // prefetch tile 0
    {
        int k = 0 + lc * 8;
        int ak = (k < KT1) ? k : k - KT1;
        cp_async16(smem_u32(&As[0][lr * LDS + lc * 8]),
                   gA + (size_t)(row0 + lr) * AK + ak);
#pragma unroll
        for (int q = 0; q < 2; q++) {
            int id = tid + q * 256;
            int r = id >> 2, c = id & 3;
            cp_async16(smem_u32(&Bs[0][r * LDS + c * 8]),
                       gB + (size_t)(col0 + r) * KTOT + c * 8);
        }
        cp_commit();
    }

    for (int kt = 0; kt < NKT; kt++) {
        int buf = kt & 1;
        cp_wait_all();
        __syncthreads();
        if (kt + 1 < NKT) {
            int k0 = (kt + 1) * BK;
            int k = k0 + lc * 8;
            int ak = (k < KT1) ? k : k - KT1;
            cp_async16(smem_u32(&As[buf ^ 1][lr * LDS + lc * 8]),
                       gA + (size_t)(row0 + lr) * AK + ak);
#pragma unroll
            for (int q = 0; q < 2; q++) {
                int id = tid + q * 256;
                int r = id >> 2, c = id & 3;
                cp_async16(smem_u32(&Bs[buf ^ 1][r * LDS + c * 8]),
                           gB + (size_t)(col0 + r) * KTOT + k0 + c * 8);
            }
            cp_commit();
        }

#pragma unroll
        for (int ks = 0; ks < 2; ks++) {
            int k0 = ks * 16;
            uint32_t a[2][4], b[4][2];
#pragma unroll
            for (int mf = 0; mf < 2; mf++) {
                int r = wm * 32 + mf * 16 + (lane & 15);
                int c = k0 + (lane >> 4) * 8;
                ldmx4(a[mf], smem_u32(&As[buf][r * LDS + c]));
            }
#pragma unroll
            for (int nb = 0; nb < 2; nb++) {
                int r = wn * 32 + nb * 16 + (lane & 7) + ((lane >> 4) << 3);
                int c = k0 + ((lane >> 3) & 1) * 8;
                uint32_t bb[4];
                ldmx4(bb, smem_u32(&Bs[buf][r * LDS + c]));
                b[2 * nb][0] = bb[0]; b[2 * nb][1] = bb[1];
                b[2 * nb + 1][0] = bb[2]; b[2 * nb + 1][1] = bb[3];
            }
#pragma unroll
            for (int mf = 0; mf < 2; mf++)
#pragma unroll
                for (int nf = 0; nf < 4; nf++)
                    mma16816(acc[mf][nf], a[mf], b[nf]);
        }
        __syncthreads();
    }

    // store
#pragma unroll
    for (int mf = 0; mf < 2; mf++) {
        int r = row0 + wm * 32 + mf * 16 + (lane >> 2);
#pragma unroll
        for (int nf = 0; nf < 4; nf++) {
            int c = col0 + wn * 32 + nf * 8 + (lane & 3) * 2;
            float* p0 = g_C + (size_t)r * JPAD + c;
            p0[0] = acc[mf][nf][0]; p0[1] = acc[mf][nf][1];
            float* p1 = g_C + (size_t)(r + 8) * JPAD + c;
            p1[0] = acc[mf][nf][2]; p1[1] = acc[mf][nf][3];
        }
    }
}

// ---------------------------------------------------------------------------
// Kernel 3: GRU gate epilogue
// ---------------------------------------------------------------------------
__global__ void epilogue(float* __restrict__ out, int N) {
    int idx = blockIdx.x * blockDim.x + threadIdx.x;
    if (idx >= N * MEM_DIM) return;
    int i = idx / MEM_DIM, c = idx % MEM_DIM;
    const float* Ci = g_C + (size_t)i * JPAD;
    float rsum = Ci[c];
    float zsum = Ci[128 + c];
    float gin  = Ci[256 + c];
    float ghn  = Ci[384 + c];
    float mem  = g_mem[(size_t)i * MEM_DIM + c];
    float r = 1.0f / (1.0f + expf(-rsum));
    float z = 1.0f / (1.0f + expf(-zsum));
    float n = tanhf(fmaf(r, ghn, gin));
    out[idx] = (1.0f - z) * n + z * mem;
}

// ---------------------------------------------------------------------------
extern "C" void kernel_launch(void* const* d_in, const int* in_sizes, int n_in,
                              void* d_out, int out_size) {
    const int*   n_id   = (const int*)d_in[0];
    const float* memory = (const float*)d_in[1];
    const float* msgs   = (const float*)d_in[2];
    const float* w1     = (const float*)d_in[3];
    const float* b1     = (const float*)d_in[4];
    const float* w2     = (const float*)d_in[5];
    const float* b2     = (const float*)d_in[6];
    const float* lg     = (const float*)d_in[7];
    const float* lb     = (const float*)d_in[8];
    const float* lng    = (const float*)d_in[9];
    const float* lnb    = (const float*)d_in[10];
    const float* wih    = (const float*)d_in[11];
    const float* whh    = (const float*)d_in[12];
    float* out = (float*)d_out;

    int N = in_sizes[0];
    if (N > N_MAXN) N = N_MAXN;

    buildB<<<(JPAD * KTOT + 255) / 256, 256>>>(wih, whh);
    phase1<<<NPAD, 128>>>(n_id, memory, msgs, w1, b1, w2, b2, lg, lb, lng, lnb, N);
    dim3 grid(NPAD / BM, JPAD / BN);
    gemm3<<<grid, 256>>>();
    epilogue<<<(N * MEM_DIM + 255) / 256, 256>>>(out, N);
}

// round 4
// speedup vs baseline: 2.0372x; 1.4180x over previous
#include <cuda_runtime.h>
#include <cuda_bf16.h>
#include <math.h>
#include <stdint.h>

// ---------------- problem constants ----------------
#define N_MAXN    50000
#define NPAD      50048          // 391 * 128
#define MEM_DIM   100
#define RAW       64
#define TIN       20
#define D_MSG     292
#define KT1       400            // K per split term (392 real + 8 pad)
#define AK        800            // A storage row: [Ahi(400) | Alo(400)]
#define KTOT      1200           // GEMM K: [Ahi*Bhi | Ahi*Blo | Alo*Bhi]
#define JPAD      512            // 4 groups at 0/128/256/384, 100 used each

// ---------------- scratch ----------------
__device__ __nv_bfloat16 g_A[(size_t)NPAD * AK];    // ~80 MB
__device__ __nv_bfloat16 g_B[(size_t)JPAD * KTOT];  // ~1.2 MB
__device__ float         g_C[(size_t)NPAD * JPAD];  // ~102 MB
__device__ float         g_mem[(size_t)NPAD * MEM_DIM];

__device__ __forceinline__ uint32_t smem_u32(const void* p) {
    uint32_t a;
    asm("{ .reg .u64 t; cvta.to.shared.u64 t, %1; cvt.u32.u64 %0, t; }" : "=r"(a) : "l"(p));
    return a;
}
__device__ __forceinline__ void cp_async16(uint32_t dst, const void* src) {
    asm volatile("cp.async.cg.shared.global [%0], [%1], 16;" :: "r"(dst), "l"(src));
}
__device__ __forceinline__ void cp_commit() {
    asm volatile("cp.async.commit_group;" ::: "memory");
}
__device__ __forceinline__ void cp_wait_all() {
    asm volatile("cp.async.wait_group 0;" ::: "memory");
}
__device__ __forceinline__ void ldmx4(uint32_t* r, uint32_t addr) {
    asm volatile("ldmatrix.sync.aligned.m8n8.x4.shared.b16 {%0,%1,%2,%3}, [%4];"
        : "=r"(r[0]), "=r"(r[1]), "=r"(r[2]), "=r"(r[3]) : "r"(addr));
}
__device__ __forceinline__ void mma16816(float* d, const uint32_t* a, const uint32_t* b) {
    asm volatile(
        "mma.sync.aligned.m16n8k16.row.col.f32.bf16.bf16.f32 "
        "{%0,%1,%2,%3}, {%4,%5,%6,%7}, {%8,%9}, {%0,%1,%2,%3};"
        : "+f"(d[0]), "+f"(d[1]), "+f"(d[2]), "+f"(d[3])
        : "r"(a[0]), "r"(a[1]), "r"(a[2]), "r"(a[3]), "r"(b[0]), "r"(b[1]));
}
__device__ __forceinline__ void bsplit(float x, __nv_bfloat16& h, __nv_bfloat16& l) {
    h = __float2bfloat16(x);
    l = __float2bfloat16(x - __bfloat162float(h));
}

// ---------------------------------------------------------------------------
// Kernel 0: pack GRU weights -> g_B [512][1200] bf16, terms [Bhi|Blo|Bhi].
// ---------------------------------------------------------------------------
__global__ void buildB(const float* __restrict__ wih, const float* __restrict__ whh) {
    int idx = blockIdx.x * blockDim.x + threadIdx.x;
    if (idx >= JPAD * KTOT) return;
    int j = idx / KTOT, k = idx % KTOT;
    int g = j >> 7, c = j & 127;
    int t = k / KT1, kk = k % KT1;
    float v = 0.0f;
    if (c < 100) {
        if (kk < D_MSG) {
            if (g == 0) v = wih[c * D_MSG + kk];
            else if (g == 1) v = wih[(100 + c) * D_MSG + kk];
            else if (g == 2) v = wih[(200 + c) * D_MSG + kk];
        } else if (kk < D_MSG + MEM_DIM) {
            int m = kk - D_MSG;
            if (g == 0) v = whh[c * MEM_DIM + m];
            else if (g == 1) v = whh[(100 + c) * MEM_DIM + m];
            else if (g == 3) v = whh[(200 + c) * MEM_DIM + m];
        }
    }
    __nv_bfloat16 h, l;
    bsplit(v, h, l);
    g_B[idx] = (t == 1) ? l : h;
}

// ---------------------------------------------------------------------------
// Kernel 1: per-node msg MLP + layernorms -> g_A row [hi(400)|lo(400)] + g_mem.
// 64 threads per node: every thread owns one msg row in the MLP.
// ---------------------------------------------------------------------------
__global__ __launch_bounds__(64) void phase1(
    const int* __restrict__ n_id,
    const float* __restrict__ memory,
    const float* __restrict__ msgs,
    const float* __restrict__ w1, const float* __restrict__ b1,
    const float* __restrict__ w2, const float* __restrict__ b2,
    const float* __restrict__ lg, const float* __restrict__ lb,
    const float* __restrict__ lng, const float* __restrict__ lnb,
    int N)
{
    __shared__ float sm[RAW * TIN];
    __shared__ float sv[D_MSG];          // [mem(100) | comp(192)]
    __shared__ float red[4];
    __shared__ float s_mu, s_rs;

    int i = blockIdx.x;
    int tid = threadIdx.x;
    size_t base = (size_t)i * AK;

    if (i >= N) {  // zero pad rows (100 uint4)
        uint4 z = make_uint4(0, 0, 0, 0);
        uint4* dst = (uint4*)(g_A + base);
        for (int k = tid; k < AK / 8; k += 64) dst[k] = z;
        return;
    }
    int row = n_id[i];

    const float4* src4 = (const float4*)(msgs + (size_t)row * (RAW * TIN));
    float4* sm4 = (float4*)sm;
#pragma unroll
    for (int t = tid; t < RAW * TIN / 4; t += 64) sm4[t] = src4[t];
    const float* memrow = memory + (size_t)row * MEM_DIM;
    for (int c = tid; c < MEM_DIM; c += 64) sv[c] = memrow[c];
    __syncthreads();

    {
        const float* mr = sm + tid * TIN;
        float h[10];
#pragma unroll
        for (int j = 0; j < 10; j++) {
            float s = __ldg(b1 + j);
#pragma unroll
            for (int t = 0; t < TIN; t++) s += mr[t] * __ldg(w1 + j * TIN + t);
            h[j] = 0.5f * s * (1.0f + erff(s * 0.7071067811865476f));
        }
        float y[3];
#pragma unroll
        for (int o = 0; o < 3; o++) {
            float s = __ldg(b2 + o);
#pragma unroll
            for (int j = 0; j < 10; j++) s += h[j] * __ldg(w2 + o * 10 + j);
            y[o] = s;
        }
        float mu = (y[0] + y[1] + y[2]) * (1.0f / 3.0f);
        float d0 = y[0] - mu, d1 = y[1] - mu, d2 = y[2] - mu;
        float var = (d0 * d0 + d1 * d1 + d2 * d2) * (1.0f / 3.0f);
        float rs = rsqrtf(var + 1e-5f);
        sv[MEM_DIM + 3 * tid + 0] = d0 * rs * __ldg(lg + 0) + __ldg(lb + 0);
        sv[MEM_DIM + 3 * tid + 1] = d1 * rs * __ldg(lg + 1) + __ldg(lb + 1);
        sv[MEM_DIM + 3 * tid + 2] = d2 * rs * __ldg(lg + 2) + __ldg(lb + 2);
    }
    __syncthreads();

    float s1 = 0.0f, s2 = 0.0f;
    for (int k = tid; k < D_MSG; k += 64) { float v = sv[k]; s1 += v; s2 += v * v; }
#pragma unroll
    for (int o = 16; o > 0; o >>= 1) {
        s1 += __shfl_down_sync(0xFFFFFFFFu, s1, o);
        s2 += __shfl_down_sync(0xFFFFFFFFu, s2, o);
    }
    if ((tid & 31) == 0) { red[tid >> 5] = s1; red[2 + (tid >> 5)] = s2; }
    __syncthreads();
    if (tid == 0) {
        float t1 = red[0] + red[1];
        float t2 = red[2] + red[3];
        float mu = t1 * (1.0f / 292.0f);
        float var = t2 * (1.0f / 292.0f) - mu * mu;
        s_mu = mu;
        s_rs = rsqrtf(var + 1e-5f);
    }
    __syncthreads();

    float mu = s_mu, rs = s_rs;
    for (int k = tid; k < D_MSG; k += 64) {
        float v = (sv[k] - mu) * rs * __ldg(lng + k) + __ldg(lnb + k);
        __nv_bfloat16 h, l; bsplit(v, h, l);
        g_A[base + k] = h; g_A[base + KT1 + k] = l;
    }
    for (int c = tid; c < MEM_DIM; c += 64) {
        float v = sv[c];
        __nv_bfloat16 h, l; bsplit(v, h, l);
        g_A[base + D_MSG + c] = h; g_A[base + KT1 + D_MSG + c] = l;
        g_mem[(size_t)i * MEM_DIM + c] = v;
    }
    if (tid < 8) {
        __nv_bfloat16 z = __float2bfloat16(0.0f);
        g_A[base + 392 + tid] = z;
        g_A[base + KT1 + 392 + tid] = z;
    }
}

// ---------------------------------------------------------------------------
// Kernel 2: bf16 HMMA GEMM  C[NPAD][512] = A * B^T   (K = 1200, 3-term split)
// BM=128 BN=128 BK=48, 256 threads, 8 warps (2x4, warp tile 64x32),
// cp.async double buffer, padded smem stride 56 halves (conflict-free).
// grid = (4 col-blocks fast, 391 row-blocks) for A reuse in L2.
// ---------------------------------------------------------------------------
#define BM 128
#define BN 128
#define BK 48
#define LDS 56
#define NKT (KTOT / BK)   // 25
#define TILE_H (BM * LDS)          // halves per A/B stage
#define SMEM_GEMM (4 * TILE_H * 2) // 2 bufs x (A+B) x 2 bytes = 57344

__global__ __launch_bounds__(256) void gemm4() {
    extern __shared__ __align__(16) uint16_t smx[];
    uint16_t* As[2] = { smx, smx + TILE_H };
    uint16_t* Bs[2] = { smx + 2 * TILE_H, smx + 3 * TILE_H };

    int tid = threadIdx.x;
    int lane = tid & 31, wid = tid >> 5;
    int wm = wid & 1, wn = wid >> 1;            // 2 x 4 warp grid
    int row0 = blockIdx.y * BM;
    int col0 = blockIdx.x * BN;

    const uint16_t* gA = (const uint16_t*)g_A;
    const uint16_t* gB = (const uint16_t*)g_B;

    float acc[4][4][4];
#pragma unroll
    for (int mf = 0; mf < 4; mf++)
#pragma unroll
        for (int nf = 0; nf < 4; nf++)
#pragma unroll
            for (int q = 0; q < 4; q++) acc[mf][nf][q] = 0.0f;

    // loader: 128 rows x 6 chunks of 8 halves = 768 chunks per tile; 3/thread.
#pragma unroll
    for (int q = 0; q < 3; q++) {
        int id = tid + q * 256;
        int r = id / 6, c = id % 6;
        int kk = c * 8;
        int ak = (kk < KT1) ? kk : kk - KT1;
        cp_async16(smem_u32(&As[0][r * LDS + c * 8]), gA + (size_t)(row0 + r) * AK + ak);
        cp_async16(smem_u32(&Bs[0][r * LDS + c * 8]), gB + (size_t)(col0 + r) * KTOT + kk);
    }
    cp_commit();

    for (int kt = 0; kt < NKT; kt++) {
        int buf = kt & 1;
        cp_wait_all();
        __syncthreads();
        if (kt + 1 < NKT) {
            int k0 = (kt + 1) * BK;
#pragma unroll
            for (int q = 0; q < 3; q++) {
                int id = tid + q * 256;
                int r = id / 6, c = id % 6;
                int kk = k0 + c * 8;
                int ak = (kk < KT1) ? kk : kk - KT1;
                cp_async16(smem_u32(&As[buf ^ 1][r * LDS + c * 8]),
                           gA + (size_t)(row0 + r) * AK + ak);
                cp_async16(smem_u32(&Bs[buf ^ 1][r * LDS + c * 8]),
                           gB + (size_t)(col0 + r) * KTOT + kk);
            }
            cp_commit();
        }

#pragma unroll
        for (int ks = 0; ks < 3; ks++) {
            int k0 = ks * 16;
            uint32_t a[4][4], b[4][2];
#pragma unroll
            for (int mf = 0; mf < 4; mf++) {
                int r = wm * 64 + mf * 16 + (lane & 15);
                int c = k0 + (lane >> 4) * 8;
                ldmx4(a[mf], smem_u32(&As[buf][r * LDS + c]));
            }
#pragma unroll
            for (int nb = 0; nb < 2; nb++) {
                int r = wn * 32 + nb * 16 + (lane & 7) + ((lane >> 4) << 3);
                int c = k0 + ((lane >> 3) & 1) * 8;
                uint32_t bb[4];
                ldmx4(bb, smem_u32(&Bs[buf][r * LDS + c]));
                b[2 * nb][0] = bb[0]; b[2 * nb][1] = bb[1];
                b[2 * nb + 1][0] = bb[2]; b[2 * nb + 1][1] = bb[3];
            }
#pragma unroll
            for (int mf = 0; mf < 4; mf++)
#pragma unroll
                for (int nf = 0; nf < 4; nf++)
                    mma16816(acc[mf][nf], a[mf], b[nf]);
        }
        __syncthreads();
    }

    // store
#pragma unroll
    for (int mf = 0; mf < 4; mf++) {
        int r = row0 + wm * 64 + mf * 16 + (lane >> 2);
#pragma unroll
        for (int nf = 0; nf < 4; nf++) {
            int c = col0 + wn * 32 + nf * 8 + (lane & 3) * 2;
            float* p0 = g_C + (size_t)r * JPAD + c;
            p0[0] = acc[mf][nf][0]; p0[1] = acc[mf][nf][1];
            float* p1 = g_C + (size_t)(r + 8) * JPAD + c;
            p1[0] = acc[mf][nf][2]; p1[1] = acc[mf][nf][3];
        }
    }
}

// ---------------------------------------------------------------------------
// Kernel 3: GRU gate epilogue
// ---------------------------------------------------------------------------
__global__ void epilogue(float* __restrict__ out, int N) {
    int idx = blockIdx.x * blockDim.x + threadIdx.x;
    if (idx >= N * MEM_DIM) return;
    int i = idx / MEM_DIM, c = idx % MEM_DIM;
    const float* Ci = g_C + (size_t)i * JPAD;
    float rsum = Ci[c];
    float zsum = Ci[128 + c];
    float gin  = Ci[256 + c];
    float ghn  = Ci[384 + c];
    float mem  = g_mem[(size_t)i * MEM_DIM + c];
    float r = 1.0f / (1.0f + expf(-rsum));
    float z = 1.0f / (1.0f + expf(-zsum));
    float n = tanhf(fmaf(r, ghn, gin));
    out[idx] = (1.0f - z) * n + z * mem;
}

// ---------------------------------------------------------------------------
extern "C" void kernel_launch(void* const* d_in, const int* in_sizes, int n_in,
                              void* d_out, int out_size) {
    const int*   n_id   = (const int*)d_in[0];
    const float* memory = (const float*)d_in[1];
    const float* msgs   = (const float*)d_in[2];
    const float* w1     = (const float*)d_in[3];
    const float* b1     = (const float*)d_in[4];
    const float* w2     = (const float*)d_in[5];
    const float* b2     = (const float*)d_in[6];
    const float* lg     = (const float*)d_in[7];
    const float* lb     = (const float*)d_in[8];
    const float* lng    = (const float*)d_in[9];
    const float* lnb    = (const float*)d_in[10];
    const float* wih    = (const float*)d_in[11];
    const float* whh    = (const float*)d_in[12];
    float* out = (float*)d_out;

    int N = in_sizes[0];
    if (N > N_MAXN) N = N_MAXN;

    cudaFuncSetAttribute(gemm4, cudaFuncAttributeMaxDynamicSharedMemorySize, SMEM_GEMM);

    buildB<<<(JPAD * KTOT + 255) / 256, 256>>>(wih, whh);
    phase1<<<NPAD, 64>>>(n_id, memory, msgs, w1, b1, w2, b2, lg, lb, lng, lnb, N);
    dim3 grid(JPAD / BN, NPAD / BM);
    gemm4<<<grid, 256, SMEM_GEMM>>>();
    epilogue<<<(N * MEM_DIM + 255) / 256, 256>>>(out, N);
}